// round 10
// baseline (speedup 1.0000x reference)
#include <cuda_runtime.h>
#include <cuda_fp16.h>

// WarpingLayer v10: serial two-pass, packed params + wavefront-lean writeback.
//   Pass 1: transpose x NCHW f32 -> xt NHWC f16 (blockIdx.y<4)
//           + param prep (blockIdx.y==4): per pixel float4 weights (validity &
//           ones-mask folded) + ONE packed int offset (o00 | dx<<15 | dy<<16).
//   Pass 2: branchless gather: broadcast param loads, 16 independent corner
//           LDGs per warp, fp16 smem staging; writeback reads half2 per thread
//           (full 128B LDS wavefronts) and stores two coalesced STG.32.
// Param math reproduces the JAX reference fp32 op ordering exactly.

namespace {

constexpr int B = 8;
constexpr int C = 128;
constexpr int H = 128;
constexpr int W = 256;
constexpr int HW = H * W;                     // 32768

// Scratch (__device__ globals: allowed).
__device__ __half g_xt[(size_t)B * HW * C];   // 67 MB transposed image
__device__ float4 g_wpar[(size_t)B * HW];     // 16.8 MB weights (4/pixel)
__device__ int    g_opar[(size_t)B * HW];     // 4.2 MB packed offsets

// ---------------- param prep: one pixel per thread ----------------
__device__ __forceinline__ void do_params(const float* __restrict__ flow,
                                          int b, int pix)
{
    const int w = pix & (W - 1);
    const int h = pix >> 8;

    const int fbase = b * 2 * HW + h * W + w;
    const float fx = __ldg(flow + fbase);
    const float fy = __ldg(flow + fbase + HW);

    // Reference-exact fp32 ordering:
    const float flo_w = __fmul_rn(__fdiv_rn(__fmul_rn(fx, 2.0f), (float)(W - 1)), 1.0f);
    const float flo_h = __fmul_rn(__fdiv_rn(__fmul_rn(fy, 2.0f), (float)(H - 1)), 1.0f);
    const float step_x = __fdiv_rn(2.0f, (float)(W - 1));
    const float step_y = __fdiv_rn(2.0f, (float)(H - 1));
    const float gx = __fadd_rn(-1.0f, __fmul_rn((float)w, step_x));
    const float gy = __fadd_rn(-1.0f, __fmul_rn((float)h, step_y));

    const float ix = __fmul_rn(__fmul_rn(__fadd_rn(__fadd_rn(gx, flo_w), 1.0f), 0.5f), (float)(W - 1));
    const float iy = __fmul_rn(__fmul_rn(__fadd_rn(__fadd_rn(gy, flo_h), 1.0f), 0.5f), (float)(H - 1));

    const float x0f = floorf(ix);
    const float y0f = floorf(iy);
    const float x1f = __fadd_rn(x0f, 1.0f);
    const float y1f = __fadd_rn(y0f, 1.0f);

    const float wx1 = __fadd_rn(ix, -x0f);
    const float wx0 = __fadd_rn(1.0f, -wx1);
    const float wy1 = __fadd_rn(iy, -y0f);
    const float wy0 = __fadd_rn(1.0f, -wy1);

    const bool vx0 = (x0f >= 0.0f) && (x0f <= (float)(W - 1));
    const bool vx1 = (x1f >= 0.0f) && (x1f <= (float)(W - 1));
    const bool vy0 = (y0f >= 0.0f) && (y0f <= (float)(H - 1));
    const bool vy1 = (y1f >= 0.0f) && (y1f <= (float)(H - 1));

    float m00 = (vx0 && vy0) ? __fmul_rn(wx0, wy0) : 0.0f;
    float m01 = (vx1 && vy0) ? __fmul_rn(wx1, wy0) : 0.0f;
    float m10 = (vx0 && vy1) ? __fmul_rn(wx0, wy1) : 0.0f;
    float m11 = (vx1 && vy1) ? __fmul_rn(wx1, wy1) : 0.0f;

    // ones_val in ref order; fold binary mask into the weights themselves.
    const float ones_val = __fadd_rn(__fadd_rn(__fadd_rn(m00, m01), m10), m11);
    if (ones_val < 0.99999f) { m00 = m01 = m10 = m11 = 0.0f; }

    const int xi0 = min(max((int)x0f, 0), W - 1);
    const int xi1 = min(max((int)x1f, 0), W - 1);
    const int yi0 = min(max((int)y0f, 0), H - 1);
    const int yi1 = min(max((int)y1f, 0), H - 1);

    const int gp = b * HW + pix;
    g_wpar[gp] = make_float4(m00, m01, m10, m11);
    // o00 in [0,32767] -> 15 bits; dx,dy in {0,1}.
    g_opar[gp] = (yi0 * W + xi0) | ((xi1 - xi0) << 15) | ((yi1 - yi0) << 16);
}

// ---------------- Pass 1: transpose + param prep ----------------
__global__ __launch_bounds__(256) void transpose_prep_kernel(
    const float* __restrict__ x,
    const float* __restrict__ flow)
{
    const int b = blockIdx.z;

    if (blockIdx.y == 4) {                     // param-prep role
        if (blockIdx.x >= 128) return;         // 128 blocks x 256 thr = 32768 px
        do_params(flow, b, blockIdx.x * 256 + threadIdx.x);
        return;
    }

    __shared__ float tile[32][133];
    const int hw0 = blockIdx.x * 128;
    const int c0  = blockIdx.y * 32;
    const int tx  = threadIdx.x & 31;
    const int ty  = threadIdx.x >> 5;          // 0..7

    const float* px = x + (size_t)b * C * HW;
    #pragma unroll
    for (int i = 0; i < 4; ++i) {
        const int cl = ty + i * 8;             // 0..31
        const float4 v = __ldcs((const float4*)(px + (size_t)(c0 + cl) * HW + hw0) + tx);
        float* t = &tile[cl][4 * tx];
        t[0] = v.x; t[1] = v.y; t[2] = v.z; t[3] = v.w;
    }
    __syncthreads();

    __half* pt = g_xt + (size_t)b * HW * C;
    const int cpair = tx & 15;                 // channel pair 0..15
    const int hwsub = tx >> 4;                 // 0..1
    #pragma unroll
    for (int i = 0; i < 8; ++i) {
        const int hwl = (i * 8 + ty) * 2 + hwsub;          // 0..127
        const __half2 hv = __floats2half2_rn(tile[cpair * 2][hwl],
                                             tile[cpair * 2 + 1][hwl]);
        *(__half2*)(pt + (size_t)(hw0 + hwl) * C + c0 + cpair * 2) = hv;
    }
}

// ---------------- Pass 2: branchless gather ----------------
// Block = 8 warps = 32 pixels (same b,h). Warp computes 4 pixels; params come
// from broadcast loads. Lane l gathers channels 4l..4l+3: one 8B uint2 load
// per corner (256B/warp, coalesced). Staging: __half tile[32][130]; gather
// stores two half2 per lane (2 full wavefronts, conflict-free); writeback
// reads ONE half2 per thread per iteration (128B/wavefront, banks
// (p+wp+8j)%32 distinct) and issues two coalesced STG.32.
__global__ __launch_bounds__(256) void warp_gather_kernel(float* __restrict__ out)
{
    __shared__ __half tile[32][130];           // 8320 B

    const int tid  = threadIdx.x;
    const int warp = tid >> 5;
    const int lane = tid & 31;

    const int pix = ((int)gridDim.x - 1 - (int)blockIdx.x) * 32;  // reversed
    const int b  = pix >> 15;
    const int h  = (pix >> 8) & (H - 1);
    const int w0 = pix & (W - 1);

    const __half* xt = g_xt + (size_t)b * HW * C;
    const int cc = lane * 4;

    #pragma unroll
    for (int pp = 0; pp < 4; ++pp) {
        const int p  = warp * 4 + pp;
        const int gp = pix + p;                // global pixel (b folded in pix)

        const float4 wv = __ldg(&g_wpar[gp]);  // broadcast (uniform address)
        const int    pk = __ldg(&g_opar[gp]);

        const int o00 = pk & 0x7FFF;
        const int dx  = (pk >> 15) & 1;
        const int o10 = o00 + ((pk >> 16) & 1) * W;
        const int o01 = o00 + dx;
        const int o11 = o10 + dx;

        // 4 independent 8B corner loads (weights already carry mask zeros).
        const uint2 r00 = *(const uint2*)(xt + (size_t)o00 * C + cc);
        const uint2 r01 = *(const uint2*)(xt + (size_t)o01 * C + cc);
        const uint2 r10 = *(const uint2*)(xt + (size_t)o10 * C + cc);
        const uint2 r11 = *(const uint2*)(xt + (size_t)o11 * C + cc);

        const float2 f00a = __half22float2(*(const __half2*)&r00.x);
        const float2 f00b = __half22float2(*(const __half2*)&r00.y);
        const float2 f01a = __half22float2(*(const __half2*)&r01.x);
        const float2 f01b = __half22float2(*(const __half2*)&r01.y);
        const float2 f10a = __half22float2(*(const __half2*)&r10.x);
        const float2 f10b = __half22float2(*(const __half2*)&r10.y);
        const float2 f11a = __half22float2(*(const __half2*)&r11.x);
        const float2 f11b = __half22float2(*(const __half2*)&r11.y);

        const float v0 = fmaf(f11a.x, wv.w, fmaf(f10a.x, wv.z, fmaf(f01a.x, wv.y, f00a.x * wv.x)));
        const float v1 = fmaf(f11a.y, wv.w, fmaf(f10a.y, wv.z, fmaf(f01a.y, wv.y, f00a.y * wv.x)));
        const float v2 = fmaf(f11b.x, wv.w, fmaf(f10b.x, wv.z, fmaf(f01b.x, wv.y, f00b.x * wv.x)));
        const float v3 = fmaf(f11b.y, wv.w, fmaf(f10b.y, wv.z, fmaf(f01b.y, wv.y, f00b.y * wv.x)));

        __half2* dst = (__half2*)&tile[p][cc];
        dst[0] = __floats2half2_rn(v0, v1);
        dst[1] = __floats2half2_rn(v2, v3);
    }

    __syncthreads();

    // Writeback: thread (warp wp, lane p) iterates channel pairs cpair=wp+8j.
    // One half2 LDS per iteration (bank (p+wp+8j)%32, conflict-free, 128B/wf),
    // two coalesced STG.32 (lanes = consecutive w).
    const int p  = tid & 31;
    const int wp = tid >> 5;
    float* po = out + (size_t)b * C * HW + (size_t)h * W + w0 + p;
    #pragma unroll
    for (int j = 0; j < 8; ++j) {
        const int cpair = wp + 8 * j;          // channels 2cpair, 2cpair+1
        const float2 f = __half22float2(*(const __half2*)&tile[p][2 * cpair]);
        __stcs(po + (size_t)(2 * cpair) * HW,     f.x);
        __stcs(po + (size_t)(2 * cpair + 1) * HW, f.y);
    }
}

}  // namespace

extern "C" void kernel_launch(void* const* d_in, const int* in_sizes, int n_in,
                              void* d_out, int out_size) {
    const float* x    = (const float*)d_in[0];
    const float* flow = (const float*)d_in[1];
    float* out        = (float*)d_out;

    dim3 tgrid(HW / 128, 5, B);                // y<4: transpose tiles, y==4: prep
    transpose_prep_kernel<<<tgrid, 256>>>(x, flow);

    const int nblocks = (B * HW) / 32;         // 8192
    warp_gather_kernel<<<nblocks, 256>>>(out);
}

// round 11
// speedup vs baseline: 1.0328x; 1.0328x over previous
#include <cuda_runtime.h>
#include <cuda_fp16.h>

// WarpingLayer v11: two-pass; params staged in smem to de-latency the gather.
//   Pass 1: transpose x NCHW f32 -> xt NHWC f16 (blockIdx.y<4)
//           + param prep (blockIdx.y==4): per pixel float4 weights (validity &
//           ones-mask folded) + ONE packed int offset (o00 | dx<<15 | dy<<16).
//   Pass 2: block cooperatively loads its 32 pixels' params into smem
//           (coalesced), then branchless gather whose corner LDGs depend only
//           on a fast LDS broadcast; fp16 smem staging; half2 writeback.
// Param math reproduces the JAX reference fp32 op ordering exactly.

namespace {

constexpr int B = 8;
constexpr int C = 128;
constexpr int H = 128;
constexpr int W = 256;
constexpr int HW = H * W;                     // 32768

// Scratch (__device__ globals: allowed).
__device__ __half g_xt[(size_t)B * HW * C];   // 67 MB transposed image
__device__ float4 g_wpar[(size_t)B * HW];     // 16.8 MB weights (4/pixel)
__device__ int    g_opar[(size_t)B * HW];     // 4.2 MB packed offsets

// ---------------- param prep: one pixel per thread ----------------
__device__ __forceinline__ void do_params(const float* __restrict__ flow,
                                          int b, int pix)
{
    const int w = pix & (W - 1);
    const int h = pix >> 8;

    const int fbase = b * 2 * HW + h * W + w;
    const float fx = __ldg(flow + fbase);
    const float fy = __ldg(flow + fbase + HW);

    // Reference-exact fp32 ordering:
    const float flo_w = __fmul_rn(__fdiv_rn(__fmul_rn(fx, 2.0f), (float)(W - 1)), 1.0f);
    const float flo_h = __fmul_rn(__fdiv_rn(__fmul_rn(fy, 2.0f), (float)(H - 1)), 1.0f);
    const float step_x = __fdiv_rn(2.0f, (float)(W - 1));
    const float step_y = __fdiv_rn(2.0f, (float)(H - 1));
    const float gx = __fadd_rn(-1.0f, __fmul_rn((float)w, step_x));
    const float gy = __fadd_rn(-1.0f, __fmul_rn((float)h, step_y));

    const float ix = __fmul_rn(__fmul_rn(__fadd_rn(__fadd_rn(gx, flo_w), 1.0f), 0.5f), (float)(W - 1));
    const float iy = __fmul_rn(__fmul_rn(__fadd_rn(__fadd_rn(gy, flo_h), 1.0f), 0.5f), (float)(H - 1));

    const float x0f = floorf(ix);
    const float y0f = floorf(iy);
    const float x1f = __fadd_rn(x0f, 1.0f);
    const float y1f = __fadd_rn(y0f, 1.0f);

    const float wx1 = __fadd_rn(ix, -x0f);
    const float wx0 = __fadd_rn(1.0f, -wx1);
    const float wy1 = __fadd_rn(iy, -y0f);
    const float wy0 = __fadd_rn(1.0f, -wy1);

    const bool vx0 = (x0f >= 0.0f) && (x0f <= (float)(W - 1));
    const bool vx1 = (x1f >= 0.0f) && (x1f <= (float)(W - 1));
    const bool vy0 = (y0f >= 0.0f) && (y0f <= (float)(H - 1));
    const bool vy1 = (y1f >= 0.0f) && (y1f <= (float)(H - 1));

    float m00 = (vx0 && vy0) ? __fmul_rn(wx0, wy0) : 0.0f;
    float m01 = (vx1 && vy0) ? __fmul_rn(wx1, wy0) : 0.0f;
    float m10 = (vx0 && vy1) ? __fmul_rn(wx0, wy1) : 0.0f;
    float m11 = (vx1 && vy1) ? __fmul_rn(wx1, wy1) : 0.0f;

    // ones_val in ref order; fold binary mask into the weights themselves.
    const float ones_val = __fadd_rn(__fadd_rn(__fadd_rn(m00, m01), m10), m11);
    if (ones_val < 0.99999f) { m00 = m01 = m10 = m11 = 0.0f; }

    const int xi0 = min(max((int)x0f, 0), W - 1);
    const int xi1 = min(max((int)x1f, 0), W - 1);
    const int yi0 = min(max((int)y0f, 0), H - 1);
    const int yi1 = min(max((int)y1f, 0), H - 1);

    const int gp = b * HW + pix;
    g_wpar[gp] = make_float4(m00, m01, m10, m11);
    // o00 in [0,32767] -> 15 bits; dx,dy in {0,1}.
    g_opar[gp] = (yi0 * W + xi0) | ((xi1 - xi0) << 15) | ((yi1 - yi0) << 16);
}

// ---------------- Pass 1: transpose + param prep ----------------
__global__ __launch_bounds__(256) void transpose_prep_kernel(
    const float* __restrict__ x,
    const float* __restrict__ flow)
{
    const int b = blockIdx.z;

    if (blockIdx.y == 4) {                     // param-prep role
        if (blockIdx.x >= 128) return;         // 128 blocks x 256 thr = 32768 px
        do_params(flow, b, blockIdx.x * 256 + threadIdx.x);
        return;
    }

    __shared__ float tile[32][133];
    const int hw0 = blockIdx.x * 128;
    const int c0  = blockIdx.y * 32;
    const int tx  = threadIdx.x & 31;
    const int ty  = threadIdx.x >> 5;          // 0..7

    const float* px = x + (size_t)b * C * HW;
    #pragma unroll
    for (int i = 0; i < 4; ++i) {
        const int cl = ty + i * 8;             // 0..31
        const float4 v = __ldcs((const float4*)(px + (size_t)(c0 + cl) * HW + hw0) + tx);
        float* t = &tile[cl][4 * tx];
        t[0] = v.x; t[1] = v.y; t[2] = v.z; t[3] = v.w;
    }
    __syncthreads();

    __half* pt = g_xt + (size_t)b * HW * C;
    const int cpair = tx & 15;                 // channel pair 0..15
    const int hwsub = tx >> 4;                 // 0..1
    #pragma unroll
    for (int i = 0; i < 8; ++i) {
        const int hwl = (i * 8 + ty) * 2 + hwsub;          // 0..127
        const __half2 hv = __floats2half2_rn(tile[cpair * 2][hwl],
                                             tile[cpair * 2 + 1][hwl]);
        *(__half2*)(pt + (size_t)(hw0 + hwl) * C + c0 + cpair * 2) = hv;
    }
}

// ---------------- Pass 2: branchless gather, smem-staged params ----------------
// Block = 8 warps = 32 pixels (same b,h). Prologue: 160 threads cooperatively
// load the block's params (128 floats + 32 ints, coalesced) into smem. Then
// each warp computes 4 pixels; corner loads depend only on LDS broadcasts.
// Lane l gathers channels 4l..4l+3 (one 8B uint2 per corner; 256B/warp).
__global__ __launch_bounds__(256, 8) void warp_gather_kernel(float* __restrict__ out)
{
    __shared__ __half tile[32][130];           // 8320 B staging
    __shared__ float  sw[128];                 // 32 px x 4 weights
    __shared__ int    so[32];                  // 32 px packed offsets

    const int tid  = threadIdx.x;
    const int warp = tid >> 5;
    const int lane = tid & 31;

    const int pix = ((int)gridDim.x - 1 - (int)blockIdx.x) * 32;  // reversed
    const int b  = pix >> 15;
    const int h  = (pix >> 8) & (H - 1);
    const int w0 = pix & (W - 1);

    // Cooperative param fetch (coalesced; weights 512B + offsets 128B).
    if (tid < 128)      sw[tid] = ((const float*)g_wpar)[(size_t)pix * 4 + tid];
    else if (tid < 160) so[tid - 128] = g_opar[pix + tid - 128];
    __syncthreads();

    const __half* xt = g_xt + (size_t)b * HW * C;
    const int cc = lane * 4;

    #pragma unroll
    for (int pp = 0; pp < 4; ++pp) {
        const int p = warp * 4 + pp;

        const float wv0 = sw[4 * p + 0];       // LDS broadcast (fast)
        const float wv1 = sw[4 * p + 1];
        const float wv2 = sw[4 * p + 2];
        const float wv3 = sw[4 * p + 3];
        const int   pk  = so[p];

        const int o00 = pk & 0x7FFF;
        const int dx  = (pk >> 15) & 1;
        const int o10 = o00 + ((pk >> 16) & 1) * W;
        const int o01 = o00 + dx;
        const int o11 = o10 + dx;

        // 4 independent 8B corner loads (weights already carry mask zeros).
        const uint2 r00 = *(const uint2*)(xt + (size_t)o00 * C + cc);
        const uint2 r01 = *(const uint2*)(xt + (size_t)o01 * C + cc);
        const uint2 r10 = *(const uint2*)(xt + (size_t)o10 * C + cc);
        const uint2 r11 = *(const uint2*)(xt + (size_t)o11 * C + cc);

        const float2 f00a = __half22float2(*(const __half2*)&r00.x);
        const float2 f00b = __half22float2(*(const __half2*)&r00.y);
        const float2 f01a = __half22float2(*(const __half2*)&r01.x);
        const float2 f01b = __half22float2(*(const __half2*)&r01.y);
        const float2 f10a = __half22float2(*(const __half2*)&r10.x);
        const float2 f10b = __half22float2(*(const __half2*)&r10.y);
        const float2 f11a = __half22float2(*(const __half2*)&r11.x);
        const float2 f11b = __half22float2(*(const __half2*)&r11.y);

        const float v0 = fmaf(f11a.x, wv3, fmaf(f10a.x, wv2, fmaf(f01a.x, wv1, f00a.x * wv0)));
        const float v1 = fmaf(f11a.y, wv3, fmaf(f10a.y, wv2, fmaf(f01a.y, wv1, f00a.y * wv0)));
        const float v2 = fmaf(f11b.x, wv3, fmaf(f10b.x, wv2, fmaf(f01b.x, wv1, f00b.x * wv0)));
        const float v3 = fmaf(f11b.y, wv3, fmaf(f10b.y, wv2, fmaf(f01b.y, wv1, f00b.y * wv0)));

        __half2* dst = (__half2*)&tile[p][cc];
        dst[0] = __floats2half2_rn(v0, v1);
        dst[1] = __floats2half2_rn(v2, v3);
    }

    __syncthreads();

    // Writeback: thread (warp wp, lane p) iterates channel pairs cpair=wp+8j.
    // One half2 LDS per iteration (bank (p+wp+8j)%32, conflict-free, 128B/wf),
    // two coalesced STG.32 (lanes = consecutive w).
    const int p  = tid & 31;
    const int wp = tid >> 5;
    float* po = out + (size_t)b * C * HW + (size_t)h * W + w0 + p;
    #pragma unroll
    for (int j = 0; j < 8; ++j) {
        const int cpair = wp + 8 * j;          // channels 2cpair, 2cpair+1
        const float2 f = __half22float2(*(const __half2*)&tile[p][2 * cpair]);
        __stcs(po + (size_t)(2 * cpair) * HW,     f.x);
        __stcs(po + (size_t)(2 * cpair + 1) * HW, f.y);
    }
}

}  // namespace

extern "C" void kernel_launch(void* const* d_in, const int* in_sizes, int n_in,
                              void* d_out, int out_size) {
    const float* x    = (const float*)d_in[0];
    const float* flow = (const float*)d_in[1];
    float* out        = (float*)d_out;

    dim3 tgrid(HW / 128, 5, B);                // y<4: transpose tiles, y==4: prep
    transpose_prep_kernel<<<tgrid, 256>>>(x, flow);

    const int nblocks = (B * HW) / 32;         // 8192
    warp_gather_kernel<<<nblocks, 256>>>(out);
}

// round 13
// speedup vs baseline: 1.0591x; 1.0255x over previous
#include <cuda_runtime.h>
#include <cuda_fp16.h>

// WarpingLayer v13 (= v12 with staging stride fixed 65 -> 67):
//   Pass 1: transpose x NCHW f32 -> xt NHWC f16 (blockIdx.y<4)
//           + param prep (blockIdx.y==4): float4 weights (validity & ones-mask
//           folded) + ONE packed int offset (o00 | dx<<15 | dy<<16) per pixel.
//   Pass 2: params staged in smem; each warp-iteration gathers TWO pixels
//           (lanes 0-15 px A, 16-31 px B; one 16B uint4 LDG per corner ->
//           half the LDG instructions); staging row stride 67 words keeps
//           swizzled offsets (up to 65) inside the row and all accesses
//           bank-conflict-free; half2 readback + coalesced STG.32 writeback.
// Param math reproduces the JAX reference fp32 op ordering exactly.

namespace {

constexpr int B = 8;
constexpr int C = 128;
constexpr int H = 128;
constexpr int W = 256;
constexpr int HW = H * W;                     // 32768
constexpr int RS = 67;                        // staging row stride (words)

// Scratch (__device__ globals: allowed).
__device__ __half g_xt[(size_t)B * HW * C];   // 67 MB transposed image
__device__ float4 g_wpar[(size_t)B * HW];     // 16.8 MB weights (4/pixel)
__device__ int    g_opar[(size_t)B * HW];     // 4.2 MB packed offsets

// ---------------- param prep: one pixel per thread ----------------
__device__ __forceinline__ void do_params(const float* __restrict__ flow,
                                          int b, int pix)
{
    const int w = pix & (W - 1);
    const int h = pix >> 8;

    const int fbase = b * 2 * HW + h * W + w;
    const float fx = __ldg(flow + fbase);
    const float fy = __ldg(flow + fbase + HW);

    // Reference-exact fp32 ordering:
    const float flo_w = __fmul_rn(__fdiv_rn(__fmul_rn(fx, 2.0f), (float)(W - 1)), 1.0f);
    const float flo_h = __fmul_rn(__fdiv_rn(__fmul_rn(fy, 2.0f), (float)(H - 1)), 1.0f);
    const float step_x = __fdiv_rn(2.0f, (float)(W - 1));
    const float step_y = __fdiv_rn(2.0f, (float)(H - 1));
    const float gx = __fadd_rn(-1.0f, __fmul_rn((float)w, step_x));
    const float gy = __fadd_rn(-1.0f, __fmul_rn((float)h, step_y));

    const float ix = __fmul_rn(__fmul_rn(__fadd_rn(__fadd_rn(gx, flo_w), 1.0f), 0.5f), (float)(W - 1));
    const float iy = __fmul_rn(__fmul_rn(__fadd_rn(__fadd_rn(gy, flo_h), 1.0f), 0.5f), (float)(H - 1));

    const float x0f = floorf(ix);
    const float y0f = floorf(iy);
    const float x1f = __fadd_rn(x0f, 1.0f);
    const float y1f = __fadd_rn(y0f, 1.0f);

    const float wx1 = __fadd_rn(ix, -x0f);
    const float wx0 = __fadd_rn(1.0f, -wx1);
    const float wy1 = __fadd_rn(iy, -y0f);
    const float wy0 = __fadd_rn(1.0f, -wy1);

    const bool vx0 = (x0f >= 0.0f) && (x0f <= (float)(W - 1));
    const bool vx1 = (x1f >= 0.0f) && (x1f <= (float)(W - 1));
    const bool vy0 = (y0f >= 0.0f) && (y0f <= (float)(H - 1));
    const bool vy1 = (y1f >= 0.0f) && (y1f <= (float)(H - 1));

    float m00 = (vx0 && vy0) ? __fmul_rn(wx0, wy0) : 0.0f;
    float m01 = (vx1 && vy0) ? __fmul_rn(wx1, wy0) : 0.0f;
    float m10 = (vx0 && vy1) ? __fmul_rn(wx0, wy1) : 0.0f;
    float m11 = (vx1 && vy1) ? __fmul_rn(wx1, wy1) : 0.0f;

    // ones_val in ref order; fold binary mask into the weights themselves.
    const float ones_val = __fadd_rn(__fadd_rn(__fadd_rn(m00, m01), m10), m11);
    if (ones_val < 0.99999f) { m00 = m01 = m10 = m11 = 0.0f; }

    const int xi0 = min(max((int)x0f, 0), W - 1);
    const int xi1 = min(max((int)x1f, 0), W - 1);
    const int yi0 = min(max((int)y0f, 0), H - 1);
    const int yi1 = min(max((int)y1f, 0), H - 1);

    const int gp = b * HW + pix;
    g_wpar[gp] = make_float4(m00, m01, m10, m11);
    // o00 in [0,32767] -> 15 bits; dx,dy in {0,1}.
    g_opar[gp] = (yi0 * W + xi0) | ((xi1 - xi0) << 15) | ((yi1 - yi0) << 16);
}

// ---------------- Pass 1: transpose + param prep ----------------
__global__ __launch_bounds__(256) void transpose_prep_kernel(
    const float* __restrict__ x,
    const float* __restrict__ flow)
{
    const int b = blockIdx.z;

    if (blockIdx.y == 4) {                     // param-prep role
        if (blockIdx.x >= 128) return;         // 128 blocks x 256 thr = 32768 px
        do_params(flow, b, blockIdx.x * 256 + threadIdx.x);
        return;
    }

    __shared__ float tile[32][133];
    const int hw0 = blockIdx.x * 128;
    const int c0  = blockIdx.y * 32;
    const int tx  = threadIdx.x & 31;
    const int ty  = threadIdx.x >> 5;          // 0..7

    const float* px = x + (size_t)b * C * HW;
    #pragma unroll
    for (int i = 0; i < 4; ++i) {
        const int cl = ty + i * 8;             // 0..31
        const float4 v = __ldcs((const float4*)(px + (size_t)(c0 + cl) * HW + hw0) + tx);
        float* t = &tile[cl][4 * tx];
        t[0] = v.x; t[1] = v.y; t[2] = v.z; t[3] = v.w;
    }
    __syncthreads();

    __half* pt = g_xt + (size_t)b * HW * C;
    const int cpair = tx & 15;                 // channel pair 0..15
    const int hwsub = tx >> 4;                 // 0..1
    #pragma unroll
    for (int i = 0; i < 8; ++i) {
        const int hwl = (i * 8 + ty) * 2 + hwsub;          // 0..127
        const __half2 hv = __floats2half2_rn(tile[cpair * 2][hwl],
                                             tile[cpair * 2 + 1][hwl]);
        *(__half2*)(pt + (size_t)(hw0 + hwl) * C + c0 + cpair * 2) = hv;
    }
}

// ---------------- Pass 2: pixel-pair branchless gather ----------------
// Block = 8 warps = 32 pixels (same b,h). Warp-iteration t handles pixel pair
// (4*warp+2t, 4*warp+2t+1): lanes 0-15 -> even px, lanes 16-31 -> odd px.
// Lane li covers channels 8*li..8*li+7: one 16B uint4 LDG per corner.
// Staging word layout RS*p + colw(li) + k, colw = 4*li + 2*(li>>3), RS=67:
//   stores (fixed k): banks = 16 even residues (px A) + same+3 odd (px B)
//   = all 32 banks; readback word RS*p + q + 2*(q>>5) -> bank (3p+const)%32,
//   a permutation over p -> conflict-free. Intra-row offsets <= 65 < 67.
__global__ __launch_bounds__(256, 7) void warp_gather_kernel(float* __restrict__ out)
{
    __shared__ unsigned stile[32 * RS];        // 8576 B staging (half2 words)
    __shared__ float    sw[128];               // 32 px x 4 weights
    __shared__ int      so[32];                // 32 px packed offsets

    const int tid  = threadIdx.x;
    const int warp = tid >> 5;
    const int lane = tid & 31;
    const int li   = lane & 15;
    const int hf   = lane >> 4;                // 0: pixel A, 1: pixel B

    const int pix = ((int)gridDim.x - 1 - (int)blockIdx.x) * 32;  // reversed
    const int b  = pix >> 15;
    const int h  = (pix >> 8) & (H - 1);
    const int w0 = pix & (W - 1);

    // Cooperative param fetch (coalesced; weights 512B + offsets 128B).
    if (tid < 128)      sw[tid] = ((const float*)g_wpar)[(size_t)pix * 4 + tid];
    else if (tid < 160) so[tid - 128] = g_opar[pix + tid - 128];
    __syncthreads();

    const __half* xt = g_xt + (size_t)b * HW * C;
    const int c8   = 8 * li;                           // channel base
    const int colw = 4 * li + 2 * (li >> 3);           // swizzled column word

    #pragma unroll
    for (int t = 0; t < 2; ++t) {
        const int p = warp * 4 + 2 * t + hf;           // this lane's pixel

        const float wv0 = sw[4 * p + 0];               // LDS (2 bcast groups)
        const float wv1 = sw[4 * p + 1];
        const float wv2 = sw[4 * p + 2];
        const float wv3 = sw[4 * p + 3];
        const int   pk  = so[p];

        const int o00 = pk & 0x7FFF;
        const int dx  = (pk >> 15) & 1;
        const int o10 = o00 + ((pk >> 16) & 1) * W;
        const int o01 = o00 + dx;
        const int o11 = o10 + dx;

        // 4 independent 16B corner loads (8 channels each).
        const uint4 r00 = *(const uint4*)(xt + (size_t)o00 * C + c8);
        const uint4 r01 = *(const uint4*)(xt + (size_t)o01 * C + c8);
        const uint4 r10 = *(const uint4*)(xt + (size_t)o10 * C + c8);
        const uint4 r11 = *(const uint4*)(xt + (size_t)o11 * C + c8);

        unsigned* row = stile + RS * p + colw;
        #pragma unroll
        for (int k = 0; k < 4; ++k) {
            const unsigned u00 = (&r00.x)[k];
            const unsigned u01 = (&r01.x)[k];
            const unsigned u10 = (&r10.x)[k];
            const unsigned u11 = (&r11.x)[k];
            const float2 f00 = __half22float2(*(const __half2*)&u00);
            const float2 f01 = __half22float2(*(const __half2*)&u01);
            const float2 f10 = __half22float2(*(const __half2*)&u10);
            const float2 f11 = __half22float2(*(const __half2*)&u11);
            const float va = fmaf(f11.x, wv3, fmaf(f10.x, wv2, fmaf(f01.x, wv1, f00.x * wv0)));
            const float vb = fmaf(f11.y, wv3, fmaf(f10.y, wv2, fmaf(f01.y, wv1, f00.y * wv0)));
            const __half2 hv = __floats2half2_rn(va, vb);
            row[k] = *(const unsigned*)&hv;            // conflict-free STS.32
        }
    }

    __syncthreads();

    // Writeback: thread (warp wp, lane p) iterates channel pairs q = wp + 8j.
    // LDS word RS*p + q + 2*(q>>5): bank (3p + const)%32 -> conflict-free.
    // Two coalesced STG.32 per pair (lanes = consecutive w).
    const int p  = tid & 31;
    const int wp = tid >> 5;
    float* po = out + (size_t)b * C * HW + (size_t)h * W + w0 + p;
    #pragma unroll
    for (int j = 0; j < 8; ++j) {
        const int q = wp + 8 * j;                      // channel pair
        const unsigned u = stile[RS * p + q + 2 * (q >> 5)];
        const float2 f = __half22float2(*(const __half2*)&u);
        __stcs(po + (size_t)(2 * q) * HW,     f.x);
        __stcs(po + (size_t)(2 * q + 1) * HW, f.y);
    }
}

}  // namespace

extern "C" void kernel_launch(void* const* d_in, const int* in_sizes, int n_in,
                              void* d_out, int out_size) {
    const float* x    = (const float*)d_in[0];
    const float* flow = (const float*)d_in[1];
    float* out        = (float*)d_out;

    dim3 tgrid(HW / 128, 5, B);                // y<4: transpose tiles, y==4: prep
    transpose_prep_kernel<<<tgrid, 256>>>(x, flow);

    const int nblocks = (B * HW) / 32;         // 8192
    warp_gather_kernel<<<nblocks, 256>>>(out);
}